// round 12
// baseline (speedup 1.0000x reference)
#include <cuda_runtime.h>
#include <cuda_fp16.h>
#include <math.h>
#include <stdint.h>

// Problem dims (fixed by setup_inputs)
#define BB 8
#define LX 512
#define NWTOK 384
#define SS 896
#define DD 1024
#define NH 16
#define HD 64
#define FFD 4096
#define NLAYER 4

// ---------------- scratch (device globals) ----------------
__device__ __half g_tgt_s[BB * SS * DD];          // fp16 residual stream
__device__ __half g_qkv[(size_t)BB * SS * 3 * DD];
__device__ __half g_attno[(size_t)BB * SS * DD];
__device__ __half g_hid[(size_t)BB * SS * FFD];
__device__ __half g_tmp_h[BB * SS * DD];
__device__ int   g_xmask[BB * LX];
__device__ __half g_embA[BB * LX * 64];           // packed x features (K=64 padded)
__device__ __half g_wnail_h[DD * 64];             // W_nail half, K padded to 64
__device__ float g_pe_t[BB * LX];                 // t value per x row
// weights fp16
__device__ __half g_wqkv[(size_t)NLAYER * 3 * DD * DD];
__device__ __half g_wo[(size_t)NLAYER * DD * DD];
__device__ __half g_w1[(size_t)NLAYER * FFD * DD];
__device__ __half g_w2[(size_t)NLAYER * DD * FFD];
// compact last-layer buffers (fp32, 8 rows)
__device__ float g_c_attn[BB * DD];
__device__ float g_c_t2[BB * DD];
__device__ float g_c_x[BB * DD];
__device__ float g_c_hid[BB * FFD];

// scores arrive pre-multiplied by 0.125*log2(e); softmax works in log2 domain
#define QSCALE 0.18033688011112042f

// ---------------- helpers ----------------
__device__ __forceinline__ uint32_t smem_u32(const void* p) {
    uint32_t a;
    asm("{ .reg .u64 t; cvta.to.shared.u64 t, %1; cvt.u32.u64 %0, t; }" : "=r"(a) : "l"(p));
    return a;
}
__device__ __forceinline__ uint32_t swz(uint32_t base, int row, int byteoff) {
    return base + row * 128 + (((byteoff >> 4) ^ (row & 7)) << 4);
}
__device__ __forceinline__ void cp_async16(uint32_t saddr, const void* gaddr) {
    asm volatile("cp.async.cg.shared.global [%0], [%1], 16;" :: "r"(saddr), "l"(gaddr));
}
__device__ __forceinline__ void cp_commit() {
    asm volatile("cp.async.commit_group;" ::: "memory");
}
template<int N>
__device__ __forceinline__ void cp_wait() {
    asm volatile("cp.async.wait_group %0;" :: "n"(N) : "memory");
}
__device__ __forceinline__ void ldsm_x4(uint32_t (&r)[4], uint32_t addr) {
    asm volatile("ldmatrix.sync.aligned.m8n8.x4.shared.b16 {%0,%1,%2,%3}, [%4];"
        : "=r"(r[0]), "=r"(r[1]), "=r"(r[2]), "=r"(r[3]) : "r"(addr));
}
__device__ __forceinline__ void ldsm_x4_trans(uint32_t (&r)[4], uint32_t addr) {
    asm volatile("ldmatrix.sync.aligned.m8n8.x4.trans.shared.b16 {%0,%1,%2,%3}, [%4];"
        : "=r"(r[0]), "=r"(r[1]), "=r"(r[2]), "=r"(r[3]) : "r"(addr));
}
__device__ __forceinline__ void mma16816(float (&d)[4], const uint32_t (&a)[4],
                                         uint32_t b0, uint32_t b1) {
    asm volatile("mma.sync.aligned.m16n8k16.row.col.f32.f16.f16.f32 "
        "{%0,%1,%2,%3}, {%4,%5,%6,%7}, {%8,%9}, {%0,%1,%2,%3};"
        : "+f"(d[0]), "+f"(d[1]), "+f"(d[2]), "+f"(d[3])
        : "r"(a[0]), "r"(a[1]), "r"(a[2]), "r"(a[3]), "r"(b0), "r"(b1));
}
__device__ __forceinline__ float gelu_exact(float x) {
    return 0.5f * x * (1.0f + erff(x * 0.70710678118654752f));
}
__device__ __forceinline__ uint32_t pack_h2(float f0, float f1) {
    __half2 h = __floats2half2_rn(f0, f1);
    return *(uint32_t*)&h;
}
__device__ __forceinline__ uint32_t ex2_h2(uint32_t t) {
    uint32_t r;
    asm("ex2.approx.f16x2 %0, %1;" : "=r"(r) : "r"(t));
    return r;
}
__device__ __forceinline__ float ex2f(float x) {
    float r;
    asm("ex2.approx.f32 %0, %1;" : "=f"(r) : "f"(x));
    return r;
}

// =====================================================================
// Dense fp16 GEMM: C = act(A @ B^T + bias) [optionally scale cols<1024 by QSCALE]
// =====================================================================
template<int ACT, int SCALEQ>
__global__ void __launch_bounds__(256, 2)
mma_gemm(const __half* __restrict__ A, const __half* __restrict__ B,
         const float* __restrict__ bias, __half* __restrict__ Ch,
         int K, int lda, int ldb, int ldc)
{
    extern __shared__ __align__(16) char sm[];
    constexpr int B_OFF = 128 * 128;
    constexpr int STAGE = 2 * B_OFF;

    const int tid = threadIdx.x;
    const int wid = tid >> 5, lane = tid & 31;
    const int warp_m = wid >> 1, warp_n = wid & 1;
    const int m0 = blockIdx.x * 128;
    const int n0 = blockIdx.y * 128;
    const uint32_t smem_base = smem_u32(sm);
    const int nch = K >> 6;

    float acc[2][8][4];
    #pragma unroll
    for (int a = 0; a < 2; a++)
        #pragma unroll
        for (int b = 0; b < 8; b++)
            #pragma unroll
            for (int c = 0; c < 4; c++) acc[a][b][c] = 0.f;

    auto load_stage = [&](int stage, int ch) {
        const int k0 = ch << 6;
        const uint32_t sbase = smem_base + stage * STAGE;
        #pragma unroll
        for (int i = tid; i < 1024; i += 256) {
            int row = i >> 3, seg = i & 7;
            cp_async16(sbase + row * 128 + ((seg ^ (row & 7)) << 4),
                       A + (long)(m0 + row) * lda + k0 + seg * 8);
        }
        #pragma unroll
        for (int i = tid; i < 1024; i += 256) {
            int row = i >> 3, seg = i & 7;
            cp_async16(sbase + B_OFF + row * 128 + ((seg ^ (row & 7)) << 4),
                       B + (long)(n0 + row) * ldb + k0 + seg * 8);
        }
        cp_commit();
    };

    auto compute = [&](int stage) {
        const uint32_t sbase = smem_base + stage * STAGE;
        const int arow = warp_m * 32 + (lane & 15);
        const int bn   = (lane & 7) + (lane >> 4) * 8;
        const int bka  = ((lane >> 3) & 1) * 8;
        #pragma unroll
        for (int kk = 0; kk < 4; kk++) {
            const int acol = kk * 16 + (lane >> 4) * 8;
            uint32_t af[2][4];
            #pragma unroll
            for (int mt = 0; mt < 2; mt++)
                ldsm_x4(af[mt], swz(sbase, arow + mt * 16, acol * 2));
            const int bk = kk * 16 + bka;
            #pragma unroll
            for (int nt2 = 0; nt2 < 4; nt2++) {
                uint32_t bf[4];
                ldsm_x4(bf, swz(sbase + B_OFF, warp_n * 64 + nt2 * 16 + bn, bk * 2));
                #pragma unroll
                for (int mt = 0; mt < 2; mt++) {
                    #pragma unroll
                    for (int j = 0; j < 2; j++)
                        mma16816(acc[mt][nt2 * 2 + j], af[mt], bf[2 * j], bf[2 * j + 1]);
                }
            }
        }
    };

    load_stage(0, 0);
    if (nch > 1) load_stage(1, 1);
    for (int ch = 0; ch < nch; ch++) {
        if (ch + 1 < nch) cp_wait<1>(); else cp_wait<0>();
        __syncthreads();
        if (ch + 2 < nch) load_stage((ch + 2) % 3, ch + 2);
        compute(ch % 3);
    }

    const int r0 = lane >> 2, c0 = (lane & 3) * 2;
    #pragma unroll
    for (int mt = 0; mt < 2; mt++) {
        #pragma unroll
        for (int nt = 0; nt < 8; nt++) {
            const int n = n0 + warp_n * 64 + nt * 8 + c0;
            float bv0 = bias ? bias[n] : 0.f;
            float bv1 = bias ? bias[n + 1] : 0.f;
            #pragma unroll
            for (int hrow = 0; hrow < 2; hrow++) {
                const int m = m0 + warp_m * 32 + mt * 16 + r0 + hrow * 8;
                float f0 = acc[mt][nt][hrow * 2 + 0] + bv0;
                float f1 = acc[mt][nt][hrow * 2 + 1] + bv1;
                if (ACT == 1) { f0 = gelu_exact(f0); f1 = gelu_exact(f1); }
                if (SCALEQ && n < DD) { f0 *= QSCALE; f1 *= QSCALE; }
                *(uint32_t*)(Ch + (long)m * ldc + n) = pack_h2(f0, f1);
            }
        }
    }
}

// =====================================================================
// Flash attention (fp16), layers 0..2
// =====================================================================
__global__ void __launch_bounds__(256, 2)
flash_kernel()
{
    extern __shared__ __align__(16) char fsm[];
    __shared__ uint32_t maskbits[16];
    constexpr int KV_OFF = 128 * 128;
    constexpr int TILE = 64 * 128;
    constexpr int KSTAGE = 2 * TILE;

    const int bh = blockIdx.y;
    const int b = bh >> 4, h = bh & 15;
    const int q0 = (gridDim.x - 1 - blockIdx.x) * 128;
    const int tid = threadIdx.x;
    const int wid = tid >> 5, lane = tid & 31;
    const uint32_t smem = smem_u32(fsm);

    if (tid < 16) {
        uint32_t m = 0;
        const int* xm = g_xmask + b * LX + tid * 32;
        #pragma unroll
        for (int i = 0; i < 32; i++) m |= (xm[i] ? 1u : 0u) << i;
        maskbits[tid] = m;
    }

    #pragma unroll
    for (int i = tid; i < 1024; i += 256) {
        int row = i >> 3, seg = i & 7;
        cp_async16(smem + row * 128 + ((seg ^ (row & 7)) << 4),
                   g_qkv + ((size_t)(b * SS + q0 + row)) * (3 * DD) + h * 64 + seg * 8);
    }
    cp_commit();

    const int nch = (q0 < LX) ? 8 : ((q0 + 128) >> 6);

    auto load_kv = [&](int c, int s) {
        const int k0 = c << 6;
        const uint32_t sb = smem + KV_OFF + s * KSTAGE;
        #pragma unroll
        for (int i = tid; i < 512; i += 256) {
            int row = i >> 3, seg = i & 7;
            cp_async16(sb + row * 128 + ((seg ^ (row & 7)) << 4),
                       g_qkv + ((size_t)(b * SS + k0 + row)) * (3 * DD) + DD + h * 64 + seg * 8);
        }
        #pragma unroll
        for (int i = tid; i < 512; i += 256) {
            int row = i >> 3, seg = i & 7;
            cp_async16(sb + TILE + row * 128 + ((seg ^ (row & 7)) << 4),
                       g_qkv + ((size_t)(b * SS + k0 + row)) * (3 * DD) + 2 * DD + h * 64 + seg * 8);
        }
        cp_commit();
    };

    load_kv(0, 0);
    load_kv(1, 1);

    float m_[2] = {-1e30f, -1e30f}, l_[2] = {0.f, 0.f};
    float out[8][4];
    #pragma unroll
    for (int j = 0; j < 8; j++)
        #pragma unroll
        for (int e = 0; e < 4; e++) out[j][e] = 0.f;

    const int r0 = lane >> 2;
    const int qrow0 = q0 + wid * 16 + r0;
    const int arow = wid * 16 + (lane & 15);
    const int bn   = (lane & 7) + (lane >> 4) * 8;
    const int bka  = ((lane >> 3) & 1) * 8;
    const int trow = (lane & 7) + ((lane >> 3) & 1) * 8;
    const int tcol = (lane >> 4) * 8;

    for (int c = 0; c < nch; c++) {
        if (c + 1 < nch) cp_wait<1>(); else cp_wait<0>();
        __syncthreads();
        if (c + 2 < nch) load_kv(c + 2, (c + 2) % 3);
        const uint32_t sb = smem + KV_OFF + (c % 3) * KSTAGE;

        float s[8][4];
        #pragma unroll
        for (int j = 0; j < 8; j++)
            #pragma unroll
            for (int e = 0; e < 4; e++) s[j][e] = 0.f;
        #pragma unroll
        for (int t = 0; t < 4; t++) {
            const int acol = t * 16 + (lane >> 4) * 8;
            uint32_t qf[4];
            ldsm_x4(qf, swz(smem, arow, acol * 2));
            const int bk = t * 16 + bka;
            #pragma unroll
            for (int j = 0; j < 4; j++) {
                uint32_t kf[4];
                ldsm_x4(kf, swz(sb, j * 16 + bn, bk * 2));
                mma16816(s[2 * j], qf, kf[0], kf[1]);
                mma16816(s[2 * j + 1], qf, kf[2], kf[3]);
            }
        }

        const int k0 = c << 6;
        uint32_t vmask;
        float cmax[2] = {-1e30f, -1e30f};
        if (k0 + 64 <= LX) {
            vmask = 0;
            #pragma unroll
            for (int j = 0; j < 8; j++) {
                #pragma unroll
                for (int e = 0; e < 4; e++) {
                    int col = k0 + j * 8 + (lane & 3) * 2 + (e & 1);
                    if (!((maskbits[col >> 5] >> (col & 31)) & 1)) {
                        vmask |= 1u << (j * 4 + e);
                        cmax[e >> 1] = fmaxf(cmax[e >> 1], s[j][e]);
                    }
                }
            }
        } else if (k0 + 64 <= q0 + wid * 16) {
            vmask = 0xffffffffu;
            #pragma unroll
            for (int j = 0; j < 8; j++) {
                #pragma unroll
                for (int e = 0; e < 4; e++)
                    cmax[e >> 1] = fmaxf(cmax[e >> 1], s[j][e]);
            }
        } else {
            vmask = 0;
            #pragma unroll
            for (int j = 0; j < 8; j++) {
                #pragma unroll
                for (int e = 0; e < 4; e++) {
                    int col = k0 + j * 8 + (lane & 3) * 2 + (e & 1);
                    int row = (e < 2) ? qrow0 : (qrow0 + 8);
                    if (col <= row) {
                        vmask |= 1u << (j * 4 + e);
                        cmax[e >> 1] = fmaxf(cmax[e >> 1], s[j][e]);
                    }
                }
            }
        }
        #pragma unroll
        for (int o = 1; o <= 2; o <<= 1) {
            cmax[0] = fmaxf(cmax[0], __shfl_xor_sync(0xffffffffu, cmax[0], o));
            cmax[1] = fmaxf(cmax[1], __shfl_xor_sync(0xffffffffu, cmax[1], o));
        }
        float mn0 = fmaxf(m_[0], cmax[0]);
        float mn1 = fmaxf(m_[1], cmax[1]);
        float f0 = ex2f(m_[0] - mn0);
        float f1 = ex2f(m_[1] - mn1);

        uint32_t ph01[8], ph23[8];
        __half2 a01 = __floats2half2_rn(0.f, 0.f);
        __half2 a23 = a01;
        #pragma unroll
        for (int j = 0; j < 8; j++) {
            float t0 = ((vmask >> (j * 4 + 0)) & 1) ? (s[j][0] - mn0) : -100.f;
            float t1 = ((vmask >> (j * 4 + 1)) & 1) ? (s[j][1] - mn0) : -100.f;
            float t2 = ((vmask >> (j * 4 + 2)) & 1) ? (s[j][2] - mn1) : -100.f;
            float t3 = ((vmask >> (j * 4 + 3)) & 1) ? (s[j][3] - mn1) : -100.f;
            ph01[j] = ex2_h2(pack_h2(t0, t1));
            ph23[j] = ex2_h2(pack_h2(t2, t3));
            a01 = __hadd2(a01, *(__half2*)&ph01[j]);
            a23 = __hadd2(a23, *(__half2*)&ph23[j]);
        }
        float2 s01 = __half22float2(a01);
        float2 s23 = __half22float2(a23);
        float rs0 = s01.x + s01.y;
        float rs1 = s23.x + s23.y;
        #pragma unroll
        for (int o = 1; o <= 2; o <<= 1) {
            rs0 += __shfl_xor_sync(0xffffffffu, rs0, o);
            rs1 += __shfl_xor_sync(0xffffffffu, rs1, o);
        }
        l_[0] = l_[0] * f0 + rs0;
        l_[1] = l_[1] * f1 + rs1;
        m_[0] = mn0; m_[1] = mn1;
        if (f0 != 1.f) {
            #pragma unroll
            for (int j = 0; j < 8; j++) { out[j][0] *= f0; out[j][1] *= f0; }
        }
        if (f1 != 1.f) {
            #pragma unroll
            for (int j = 0; j < 8; j++) { out[j][2] *= f1; out[j][3] *= f1; }
        }

        #pragma unroll
        for (int t = 0; t < 4; t++) {
            uint32_t pf[4] = { ph01[2 * t], ph23[2 * t], ph01[2 * t + 1], ph23[2 * t + 1] };
            #pragma unroll
            for (int j = 0; j < 4; j++) {
                uint32_t vf[4];
                ldsm_x4_trans(vf, swz(sb + TILE, t * 16 + trow, (j * 16 + tcol) * 2));
                mma16816(out[2 * j], pf, vf[0], vf[1]);
                mma16816(out[2 * j + 1], pf, vf[2], vf[3]);
            }
        }
    }

    float inv0 = 1.f / l_[0];
    float inv1 = 1.f / l_[1];
    #pragma unroll
    for (int j = 0; j < 8; j++) {
        const int d = h * 64 + j * 8 + (lane & 3) * 2;
        *(uint32_t*)(g_attno + ((size_t)(b * SS + qrow0)) * DD + d) =
            pack_h2(out[j][0] * inv0, out[j][1] * inv0);
        *(uint32_t*)(g_attno + ((size_t)(b * SS + qrow0 + 8)) * DD + d) =
            pack_h2(out[j][2] * inv1, out[j][3] * inv1);
    }
}

// =====================================================================
// Last layer: attention for ONLY the final token of each batch.
// =====================================================================
__global__ void flash_last_kernel(const float* __restrict__ Wq,
                                  const float* __restrict__ bq)
{
    __shared__ float xrow[DD];
    __shared__ float q[HD];
    __shared__ float probs[SS];
    __shared__ float red[256];
    const int bh = blockIdx.x;
    const int b = bh >> 4, h = bh & 15;
    const int tid = threadIdx.x;

    const __half* trow = g_tgt_s + ((size_t)b * SS + SS - 1) * DD;
    for (int i = tid; i < DD; i += 256) xrow[i] = __half2float(trow[i]);
    __syncthreads();

    {
        int d = tid >> 2, part = tid & 3;
        const float* wr = Wq + (size_t)(h * HD + d) * DD;
        float s = 0.f;
        for (int k = part; k < DD; k += 4) s = fmaf(xrow[k], wr[k], s);
        s += __shfl_xor_sync(0xffffffffu, s, 1);
        s += __shfl_xor_sync(0xffffffffu, s, 2);
        if (part == 0) q[d] = (s + bq[h * HD + d]) * 0.125f;
    }
    __syncthreads();

    const int* xm = g_xmask + b * LX;
    float lmax = -1e30f;
    for (int k = tid; k < SS; k += 256) {
        bool valid = (k < LX) ? (xm[k] == 0) : true;
        float s = 0.f;
        const __half* krow = g_qkv + ((size_t)(b * SS + k)) * (3 * DD) + DD + h * 64;
        #pragma unroll 16
        for (int d = 0; d < HD; d++) s = fmaf(q[d], __half2float(krow[d]), s);
        probs[k] = valid ? s : -1e30f;
        if (valid) lmax = fmaxf(lmax, s);
    }
    red[tid] = lmax; __syncthreads();
    for (int o = 128; o > 0; o >>= 1) { if (tid < o) red[tid] = fmaxf(red[tid], red[tid + o]); __syncthreads(); }
    float mx = red[0]; __syncthreads();
    float lsum = 0.f;
    for (int k = tid; k < SS; k += 256) {
        float p = (probs[k] > -1e29f) ? __expf(probs[k] - mx) : 0.f;
        probs[k] = p; lsum += p;
    }
    red[tid] = lsum; __syncthreads();
    for (int o = 128; o > 0; o >>= 1) { if (tid < o) red[tid] += red[tid + o]; __syncthreads(); }
    float inv = 1.f / red[0]; __syncthreads();

    {
        int d = tid >> 2, part = tid & 3;
        float s = 0.f;
        for (int k = part; k < SS; k += 4) {
            const __half* vrow = g_qkv + ((size_t)(b * SS + k)) * (3 * DD) + 2 * DD + h * 64;
            s = fmaf(probs[k], __half2float(vrow[d]), s);
        }
        s += __shfl_xor_sync(0xffffffffu, s, 1);
        s += __shfl_xor_sync(0xffffffffu, s, 2);
        if (part == 0) g_c_attn[b * DD + h * HD + d] = s * inv;
    }
}

// ---------------- small GEMM on 8 compact rows ----------------
template<int ACT>
__global__ void small_gemm(const float* __restrict__ in, const float* __restrict__ W,
                           const float* __restrict__ bias, float* __restrict__ out,
                           int N, int K)
{
    int n = blockIdx.x;
    int wid = threadIdx.x >> 5, lane = threadIdx.x & 31;
    const float* wrow = W + (size_t)n * K;
    const float* irow = in + (size_t)wid * K;
    float s = 0.f;
    for (int k = lane; k < K; k += 32) s = fmaf(irow[k], wrow[k], s);
    #pragma unroll
    for (int o = 16; o > 0; o >>= 1) s += __shfl_xor_sync(0xffffffffu, s, o);
    if (lane == 0) {
        float v = s + bias[n];
        if (ACT) v = gelu_exact(v);
        out[(size_t)wid * N + n] = v;
    }
}

// ---------------- compact residual + LN (base: half if baseH, else float) ----------------
__global__ void resid_ln_last(const __half* __restrict__ baseH, long baseStride,
                              const float* __restrict__ baseF,
                              const float* __restrict__ delta,
                              const float* __restrict__ g, const float* __restrict__ beta,
                              float* __restrict__ dst)
{
    int b = blockIdx.x;
    int tid = threadIdx.x;
    const float* dr = delta + (size_t)b * DD;
    float v[4];
    float s = 0.f;
    #pragma unroll
    for (int i = 0; i < 4; i++) {
        int idx = tid + i * 256;
        float base = baseH ? __half2float(baseH[(size_t)b * baseStride + idx])
                           : baseF[(size_t)b * DD + idx];
        v[i] = base + dr[idx];
        s += v[i];
    }
    __shared__ float red[256];
    red[tid] = s; __syncthreads();
    #pragma unroll
    for (int o = 128; o > 0; o >>= 1) { if (tid < o) red[tid] += red[tid + o]; __syncthreads(); }
    float mean = red[0] * (1.f / 1024.f);
    __syncthreads();
    float s2 = 0.f;
    #pragma unroll
    for (int i = 0; i < 4; i++) { float d = v[i] - mean; s2 += d * d; }
    red[tid] = s2; __syncthreads();
    #pragma unroll
    for (int o = 128; o > 0; o >>= 1) { if (tid < o) red[tid] += red[tid + o]; __syncthreads(); }
    float inv = rsqrtf(red[0] * (1.f / 1024.f) + 1e-5f);
    #pragma unroll
    for (int i = 0; i < 4; i++) {
        int idx = tid + i * 256;
        dst[(size_t)b * DD + idx] = (v[i] - mean) * inv * g[idx] + beta[idx];
    }
}

// ---------------- fp32 -> fp16 ----------------
__global__ void cvt_kernel(const float* __restrict__ src,
                           __half* __restrict__ h, long n4)
{
    long i = (long)blockIdx.x * blockDim.x + threadIdx.x;
    if (i >= n4) return;
    float4 v = *(const float4*)(src + i * 4);
    uint2 hv;
    hv.x = pack_h2(v.x, v.y);
    hv.y = pack_h2(v.z, v.w);
    *(uint2*)(h + i * 4) = hv;
}

// ---------------- prep x: pack features to half [4096 x 64], mask, t ----------------
__global__ void prep_x_kernel(const float* __restrict__ x)
{
    const float RSC = 0.99995000374968753f;
    int row = blockIdx.x;          // b*LX + l
    int tid = threadIdx.x;         // 64
    const float* xr = x + (long)row * 64;
    if (tid == 0) {
        float t0 = xr[0];
        g_xmask[row] = isnan(t0) ? 1 : 0;
        g_pe_t[row] = isnan(t0) ? 0.f : t0;
    }
    float v = 0.f;
    if (tid < 63) {
        float u = xr[tid + 1];
        if (isnan(u)) u = 0.f;
        u *= RSC;
        v = fminf(fmaxf(u, -5.f), 5.f);
    }
    g_embA[row * 64 + tid] = __float2half_rn(v);
}

// ---------------- pad W_nail to half [1024 x 64] ----------------
__global__ void prep_wnail_kernel(const float* __restrict__ W_nail)
{
    int d = blockIdx.x;
    int k = threadIdx.x;   // 64
    g_wnail_h[d * 64 + k] = __float2half_rn(k < 63 ? W_nail[d * 63 + k] : 0.f);
}

// ---------------- PE add for x tokens: tmp_h[4096x1024] + PE -> tgt_s ----------------
__global__ void pe_x_kernel()
{
    int row = blockIdx.x;          // b*LX + l
    int b = row / LX, l = row % LX;
    int tid = threadIdx.x;         // 256
    float t = g_pe_t[row];
    const float kfac = -logf(1000.f) / 1024.f;
    const __half* src = g_tmp_h + (size_t)row * DD;
    __half* dst = g_tgt_s + ((size_t)b * SS + l) * DD;
    for (int d = tid; d < DD; d += 256) {
        int i = d >> 1;
        float ang = t * expf((float)i * kfac);
        float pe = (d & 1) ? cosf(ang) : sinf(ang);
        dst[d] = __float2half_rn(__half2float(src[d]) + pe);
    }
}

// ---------------- embedding: w tokens + global PE (half out) ----------------
__global__ void embed_w_kernel(const float* __restrict__ w,
                               const float* __restrict__ W_cond,
                               const float* __restrict__ b_cond)
{
    const float RSC = 0.99995000374968753f;
    int row = blockIdx.x;
    int b = row / NWTOK, r = row % NWTOK;
    const float* wr6 = w + (long)b * (NWTOK * 6) + r * 6;
    __shared__ float wn[6];
    int tid = threadIdx.x;
    if (tid < 6) {
        float v = wr6[tid];
        if (isnan(v)) v = 0.f;
        v *= RSC;
        wn[tid] = fminf(fmaxf(v, -5.f), 5.f);
    }
    __syncthreads();
    int spos = LX + r;
    const float kfac = -logf(1000.f) / 1024.f;
    for (int d = tid; d < DD; d += 256) {
        const float* wc = W_cond + d * 6;
        float acc = b_cond[d];
        #pragma unroll
        for (int c = 0; c < 6; c++) acc = fmaf(wn[c], wc[c], acc);
        int i = d >> 1;
        float ang = (float)spos * expf((float)i * kfac);
        acc += (d & 1) ? cosf(ang) : sinf(ang);
        g_tgt_s[((size_t)b * SS + spos) * DD + d] = __float2half_rn(acc);
    }
}

// ---------------- residual add + LayerNorm (fp16 stream, fp32 math) ----------------
__global__ void resid_ln_kernel(const __half* __restrict__ delta,
                                const float* __restrict__ g,
                                const float* __restrict__ beta)
{
    size_t row = blockIdx.x;
    __half* t = g_tgt_s + row * DD;
    const __half* dl = delta + row * DD;
    int tid = threadIdx.x;
    float v[4];
    float s = 0.f;
    #pragma unroll
    for (int i = 0; i < 4; i++) {
        int idx = tid + i * 256;
        v[i] = __half2float(t[idx]) + __half2float(dl[idx]);
        s += v[i];
    }
    __shared__ float red[256];
    red[tid] = s; __syncthreads();
    #pragma unroll
    for (int o = 128; o > 0; o >>= 1) { if (tid < o) red[tid] += red[tid + o]; __syncthreads(); }
    float mean = red[0] * (1.f / 1024.f);
    __syncthreads();
    float s2 = 0.f;
    #pragma unroll
    for (int i = 0; i < 4; i++) { float d = v[i] - mean; s2 += d * d; }
    red[tid] = s2; __syncthreads();
    #pragma unroll
    for (int o = 128; o > 0; o >>= 1) { if (tid < o) red[tid] += red[tid + o]; __syncthreads(); }
    float inv = rsqrtf(red[0] * (1.f / 1024.f) + 1e-5f);
    #pragma unroll
    for (int i = 0; i < 4; i++) {
        int idx = tid + i * 256;
        t[idx] = __float2half_rn((v[i] - mean) * inv * g[idx] + beta[idx]);
    }
}

// ---------------- head + loss (reads compact final rows) ----------------
__global__ void loss_kernel(const float* __restrict__ W_ham, const float* __restrict__ b_ham,
                            const float* __restrict__ y, const float* __restrict__ w,
                            float* __restrict__ out)
{
    __shared__ float red[256];
    int tid = threadIdx.x;
    float acc = 0.f;
    for (int idx = tid; idx < BB * 144; idx += 256) {
        int b = idx / 144;
        int j = idx % 144;
        const float* row = g_c_x + (size_t)b * DD;
        const float* wr = W_ham + (size_t)j * DD;
        float dot = b_ham[j];
        for (int k = 0; k < DD; k++) dot = fmaf(row[k], wr[k], dot);
        float yr = y[b * 144 + j] - w[(size_t)b * 2304 + 2160 + j];
        float d = dot - yr;
        acc += d * d;
    }
    red[tid] = acc; __syncthreads();
    #pragma unroll
    for (int o = 128; o > 0; o >>= 1) { if (tid < o) red[tid] += red[tid + o]; __syncthreads(); }
    if (tid == 0) out[0] = red[0] / (float)(BB * 144);
}

// ---------------- launch ----------------
extern "C" void kernel_launch(void* const* d_in, const int* in_sizes, int n_in,
                              void* d_out, int out_size)
{
    const float* x      = (const float*)d_in[0];
    const float* w      = (const float*)d_in[1];
    const float* y      = (const float*)d_in[2];
    const float* W_nail = (const float*)d_in[3];
    const float* b_nail = (const float*)d_in[4];
    const float* W_cond = (const float*)d_in[5];
    const float* b_cond = (const float*)d_in[6];
    const float* Wqkv   = (const float*)d_in[7];
    const float* bqkv   = (const float*)d_in[8];
    const float* Wo     = (const float*)d_in[9];
    const float* bo     = (const float*)d_in[10];
    const float* ln1_g  = (const float*)d_in[11];
    const float* ln1_b  = (const float*)d_in[12];
    const float* ln2_g  = (const float*)d_in[13];
    const float* ln2_b  = (const float*)d_in[14];
    const float* W1     = (const float*)d_in[15];
    const float* b1     = (const float*)d_in[16];
    const float* W2     = (const float*)d_in[17];
    const float* b2     = (const float*)d_in[18];
    const float* W_ham  = (const float*)d_in[19];
    const float* b_ham  = (const float*)d_in[20];

    float *p_c_attn, *p_c_t2, *p_c_x, *p_c_hid;
    __half *p_tgt_s, *p_qkv, *p_attno, *p_hid, *p_tmp_h, *p_embA, *p_wnail;
    __half *p_wqkv, *p_wo, *p_w1, *p_w2;
    cudaGetSymbolAddress((void**)&p_tgt_s,  g_tgt_s);
    cudaGetSymbolAddress((void**)&p_qkv,    g_qkv);
    cudaGetSymbolAddress((void**)&p_attno,  g_attno);
    cudaGetSymbolAddress((void**)&p_hid,    g_hid);
    cudaGetSymbolAddress((void**)&p_tmp_h,  g_tmp_h);
    cudaGetSymbolAddress((void**)&p_embA,   g_embA);
    cudaGetSymbolAddress((void**)&p_wnail,  g_wnail_h);
    cudaGetSymbolAddress((void**)&p_wqkv,   g_wqkv);
    cudaGetSymbolAddress((void**)&p_wo,     g_wo);
    cudaGetSymbolAddress((void**)&p_w1,     g_w1);
    cudaGetSymbolAddress((void**)&p_w2,     g_w2);
    cudaGetSymbolAddress((void**)&p_c_attn, g_c_attn);
    cudaGetSymbolAddress((void**)&p_c_t2,   g_c_t2);
    cudaGetSymbolAddress((void**)&p_c_x,    g_c_x);
    cudaGetSymbolAddress((void**)&p_c_hid,  g_c_hid);

    static const int SMG = 32768 * 3;
    static const int SMF = 16384 + 3 * 16384;
    cudaFuncSetAttribute(mma_gemm<0, 0>, cudaFuncAttributeMaxDynamicSharedMemorySize, SMG);
    cudaFuncSetAttribute(mma_gemm<0, 1>, cudaFuncAttributeMaxDynamicSharedMemorySize, SMG);
    cudaFuncSetAttribute(mma_gemm<1, 0>, cudaFuncAttributeMaxDynamicSharedMemorySize, SMG);
    cudaFuncSetAttribute(flash_kernel,   cudaFuncAttributeMaxDynamicSharedMemorySize, SMF);

    const int M = BB * SS;   // 7168
    dim3 blk(256);

    // weight conversions
    {
        long n;
        n = (long)NLAYER * 3 * DD * DD / 4;
        cvt_kernel<<<(unsigned)((n + 255) / 256), blk>>>(Wqkv, p_wqkv, n);
        n = (long)(NLAYER - 1) * DD * DD / 4;
        cvt_kernel<<<(unsigned)((n + 255) / 256), blk>>>(Wo, p_wo, n);
        n = (long)(NLAYER - 1) * FFD * DD / 4;
        cvt_kernel<<<(unsigned)((n + 255) / 256), blk>>>(W1, p_w1, n);
        n = (long)(NLAYER - 1) * DD * FFD / 4;
        cvt_kernel<<<(unsigned)((n + 255) / 256), blk>>>(W2, p_w2, n);
    }

    // embeddings: x via GEMM, w via SIMT
    prep_x_kernel<<<BB * LX, 64>>>(x);
    prep_wnail_kernel<<<DD, 64>>>(W_nail);
    mma_gemm<0, 0><<<dim3(BB * LX / 128, DD / 128), blk, SMG>>>(
        p_embA, p_wnail, b_nail, p_tmp_h, 64, 64, 64, DD);
    pe_x_kernel<<<BB * LX, blk>>>();
    embed_w_kernel<<<BB * NWTOK, blk>>>(w, W_cond, b_cond);

    // ---- layers 0..2: full pipeline ----
    for (int l = 0; l < NLAYER - 1; l++) {
        const __half* wqkv_l = p_wqkv + (size_t)l * 3 * DD * DD;
        const __half* wo_l   = p_wo + (size_t)l * DD * DD;
        const __half* w1_l   = p_w1 + (size_t)l * FFD * DD;
        const __half* w2_l   = p_w2 + (size_t)l * DD * FFD;

        mma_gemm<0, 1><<<dim3(M / 128, 3 * DD / 128), blk, SMG>>>(
            p_tgt_s, wqkv_l, bqkv + (size_t)l * 3 * DD,
            p_qkv, DD, DD, DD, 3 * DD);

        flash_kernel<<<dim3(SS / 128, BB * NH), blk, SMF>>>();

        mma_gemm<0, 0><<<dim3(M / 128, DD / 128), blk, SMG>>>(
            p_attno, wo_l, bo + (size_t)l * DD,
            p_tmp_h, DD, DD, DD, DD);

        resid_ln_kernel<<<M, blk>>>(p_tmp_h, ln1_g + (size_t)l * DD, ln1_b + (size_t)l * DD);

        mma_gemm<1, 0><<<dim3(M / 128, FFD / 128), blk, SMG>>>(
            p_tgt_s, w1_l, b1 + (size_t)l * FFD,
            p_hid, DD, DD, DD, FFD);

        mma_gemm<0, 0><<<dim3(M / 128, DD / 128), blk, SMG>>>(
            p_hid, w2_l, b2 + (size_t)l * DD,
            p_tmp_h, FFD, FFD, FFD, DD);

        resid_ln_kernel<<<M, blk>>>(p_tmp_h, ln2_g + (size_t)l * DD, ln2_b + (size_t)l * DD);
    }

    // ---- layer 3: only the final token per batch matters downstream ----
    {
        const int l = NLAYER - 1;
        mma_gemm<0, 0><<<dim3(M / 128, 2 * DD / 128), blk, SMG>>>(
            p_tgt_s, p_wqkv + (size_t)l * 3 * DD * DD + (size_t)DD * DD,
            bqkv + (size_t)l * 3 * DD + DD,
            p_qkv + DD, DD, DD, DD, 3 * DD);

        flash_last_kernel<<<BB * NH, blk>>>(
            Wqkv + (size_t)l * 3 * DD * DD, bqkv + (size_t)l * 3 * DD);

        small_gemm<0><<<DD, blk>>>(p_c_attn, Wo + (size_t)l * DD * DD,
                                   bo + (size_t)l * DD, p_c_t2, DD, DD);
        resid_ln_last<<<BB, blk>>>(p_tgt_s + (size_t)(SS - 1) * DD, (long)SS * DD,
                                   nullptr,
                                   p_c_t2, ln1_g + (size_t)l * DD, ln1_b + (size_t)l * DD,
                                   p_c_x);
        small_gemm<1><<<FFD, blk>>>(p_c_x, W1 + (size_t)l * FFD * DD,
                                    b1 + (size_t)l * FFD, p_c_hid, FFD, DD);
        small_gemm<0><<<DD, blk>>>(p_c_hid, W2 + (size_t)l * DD * FFD,
                                   b2 + (size_t)l * DD, p_c_t2, DD, FFD);
        resid_ln_last<<<BB, blk>>>(nullptr, 0,
                                   p_c_x,
                                   p_c_t2, ln2_g + (size_t)l * DD, ln2_b + (size_t)l * DD,
                                   p_c_x);
    }

    loss_kernel<<<1, blk>>>(W_ham, b_ham, y, w, (float*)d_out);
}